// round 7
// baseline (speedup 1.0000x reference)
#include <cuda_runtime.h>
#include <cuda_bf16.h>
#include <stdint.h>
#include <math.h>

#define DIM   1024
#define NPAT  8192
#define NROWS 8192

__device__ __nv_bfloat16 g_xb  [(size_t)NROWS * DIM];
__device__ __nv_bfloat16 g_wqb [(size_t)DIM * DIM];
__device__ __nv_bfloat16 g_xib [(size_t)NPAT * DIM];
__device__ __nv_bfloat16 g_xitb[(size_t)DIM * NPAT];
__device__ __nv_bfloat16 g_qb  [(size_t)NROWS * DIM];
__device__ __nv_bfloat16 g_p   [(size_t)NROWS * NPAT];
__device__ float g_rowsum[NROWS];
__device__ float g_colsum[DIM];

__device__ __forceinline__ uint32_t smem_u32(const void* p) {
    uint32_t a;
    asm("{ .reg .u64 t; cvta.to.shared.u64 t, %1; cvt.u32.u64 %0, t; }" : "=r"(a) : "l"(p));
    return a;
}
__device__ __forceinline__ uint32_t sw128(uint32_t o) { return o ^ ((o >> 3) & 0x70); }

#define LDMX4(r, a)                                                               \
    asm volatile("ldmatrix.sync.aligned.m8n8.x4.shared.b16 {%0,%1,%2,%3}, [%4];"  \
        : "=r"((r)[0]), "=r"((r)[1]), "=r"((r)[2]), "=r"((r)[3]) : "r"(a))

#define MMA16816(d, a, b0, b1)                                                    \
    asm volatile("mma.sync.aligned.m16n8k16.row.col.f32.bf16.bf16.f32 "           \
        "{%0,%1,%2,%3}, {%4,%5,%6,%7}, {%8,%9}, {%0,%1,%2,%3};"                   \
        : "+f"((d)[0]), "+f"((d)[1]), "+f"((d)[2]), "+f"((d)[3])                  \
        : "r"((a)[0]), "r"((a)[1]), "r"((a)[2]), "r"((a)[3]), "r"(b0), "r"(b1))

#define CP_ASYNC(s, g) \
    asm volatile("cp.async.cg.shared.global [%0], [%1], 16;" :: "r"(s), "l"(g))
#define CP_COMMIT() asm volatile("cp.async.commit_group;")
#define CP_WAIT(n)  asm volatile("cp.async.wait_group %0;" :: "n"(n))

// ---------------- prep kernels ----------------
__global__ void zero_kernel() {
    int i = blockIdx.x * blockDim.x + threadIdx.x;
    if (i < NROWS) g_rowsum[i] = 0.f;
    if (i < DIM)   g_colsum[i] = 0.f;
}
__global__ void cvt_kernel(const float4* __restrict__ src, __nv_bfloat162* __restrict__ dst, int n4) {
    int i = blockIdx.x * blockDim.x + threadIdx.x;
    if (i < n4) {
        float4 v = src[i];
        dst[2 * i]     = __floats2bfloat162_rn(v.x, v.y);
        dst[2 * i + 1] = __floats2bfloat162_rn(v.z, v.w);
    }
}
__global__ void transpose_kernel(const float* __restrict__ xi) {
    __shared__ __nv_bfloat16 t[32][33];
    int p0 = blockIdx.x * 32, d0 = blockIdx.y * 32;
    int tx = threadIdx.x, ty = threadIdx.y;
#pragma unroll
    for (int i = 0; i < 4; i++)
        t[ty + 8 * i][tx] = __float2bfloat16(xi[(size_t)(p0 + ty + 8 * i) * DIM + d0 + tx]);
    __syncthreads();
#pragma unroll
    for (int i = 0; i < 4; i++)
        g_xitb[(size_t)(d0 + ty + 8 * i) * NPAT + p0 + tx] = t[tx][ty + 8 * i];
}
__global__ void colsum_kernel(const float* __restrict__ xi) {
    int t = threadIdx.x;
    int r0 = blockIdx.x * 128;
    float4 a = make_float4(0.f, 0.f, 0.f, 0.f);
    for (int r = 0; r < 128; r++) {
        float4 v = ((const float4*)xi)[(size_t)(r0 + r) * (DIM / 4) + t];
        a.x += v.x; a.y += v.y; a.z += v.z; a.w += v.w;
    }
    atomicAdd(&g_colsum[4 * t + 0], a.x);
    atomicAdd(&g_colsum[4 * t + 1], a.y);
    atomicAdd(&g_colsum[4 * t + 2], a.z);
    atomicAdd(&g_colsum[4 * t + 3], a.w);
}

// =============================================================================
// bf16 HMMA GEMM: C[128x256] = A[128xK] * B[256xK]^T (row-major, K contiguous)
// 256 threads = 8 warps (2m x 4n), warp tile 64x64, mma.m16n8k16, fp32 accum.
// 3-stage cp.async pipeline, BK=64, SW128 smem (16KB A + 32KB B)/stage.
// One __syncthreads per K-chunk.
// =============================================================================
#define BM 128
#define BN 256
#define A_STG 16384
#define B_STG 32768
#define STAGE_BYTES (A_STG + B_STG)
#define STAGES 3
#define DSMEM (STAGES * STAGE_BYTES)

__device__ __forceinline__ void issue_stage(uint32_t sdst,
        const __nv_bfloat16* __restrict__ Ag, const __nv_bfloat16* __restrict__ Bg,
        int lda, int ldb, int bm, int bn, int k0, int tid) {
#pragma unroll
    for (int t = 0; t < 4; t++) {
        int id = tid + t * 256, row = id >> 3, c = id & 7;
        CP_ASYNC(sdst + sw128(row * 128 + c * 16),
                 Ag + (size_t)(bm + row) * lda + k0 + c * 8);
    }
#pragma unroll
    for (int t = 0; t < 8; t++) {
        int id = tid + t * 256, row = id >> 3, c = id & 7;
        CP_ASYNC(sdst + A_STG + sw128(row * 128 + c * 16),
                 Bg + (size_t)(bn + row) * ldb + k0 + c * 8);
    }
}

template <int EPI>
__global__ __launch_bounds__(256, 1) void hgemm(
        const __nv_bfloat16* __restrict__ A, const __nv_bfloat16* __restrict__ B,
        int lda, int ldb, int nk,
        const float* __restrict__ beta_ptr, float* __restrict__ outp) {
    extern __shared__ char sm[];
    const uint32_t sb = smem_u32(sm);
    const int tid = threadIdx.x, lane = tid & 31, w = tid >> 5;
    const int wm = w & 1, wn = w >> 1;          // 2 x 4 warps, warp tile 64x64
    const int bm = blockIdx.y * BM, bn = blockIdx.x * BN;

    float acc[4][8][4];
#pragma unroll
    for (int mt = 0; mt < 4; mt++)
#pragma unroll
        for (int nt = 0; nt < 8; nt++)
#pragma unroll
            for (int j = 0; j < 4; j++) acc[mt][nt][j] = 0.f;

    issue_stage(sb, A, B, lda, ldb, bm, bn, 0, tid);  CP_COMMIT();
    issue_stage(sb + STAGE_BYTES, A, B, lda, ldb, bm, bn, 64, tid);  CP_COMMIT();

    const uint32_t abase0 = (wm * 64 + (lane & 15)) * 128 + (lane >> 4) * 16;
    const uint32_t bbase0 = (wn * 64 + ((lane >> 4) & 1) * 8 + (lane & 7)) * 128 +
                            ((lane >> 3) & 1) * 16;

    for (int i = 0; i < nk; i++) {
        if (i == nk - 1) { CP_WAIT(0); } else { CP_WAIT(1); }
        __syncthreads();
        if (i + 2 < nk) {
            issue_stage(sb + ((i + 2) % STAGES) * STAGE_BYTES, A, B, lda, ldb, bm, bn,
                        (i + 2) * 64, tid);
            CP_COMMIT();
        }
        const uint32_t sA = sb + (i % STAGES) * STAGE_BYTES;
        const uint32_t sB = sA + A_STG;
#pragma unroll
        for (int ks = 0; ks < 4; ks++) {
            uint32_t a[4][4], b[4][4];
#pragma unroll
            for (int mt = 0; mt < 4; mt++)
                LDMX4(a[mt], sA + sw128(abase0 + mt * 16 * 128 + ks * 32));
#pragma unroll
            for (int nt2 = 0; nt2 < 4; nt2++)
                LDMX4(b[nt2], sB + sw128(bbase0 + nt2 * 16 * 128 + ks * 32));
#pragma unroll
            for (int mt = 0; mt < 4; mt++)
#pragma unroll
                for (int nt = 0; nt < 8; nt++)
                    MMA16816(acc[mt][nt], a[mt], b[nt >> 1][(nt & 1) * 2],
                             b[nt >> 1][(nt & 1) * 2 + 1]);
        }
    }

    // ------------------------------ epilogue ------------------------------
    const int rbase   = bm + wm * 64 + (lane >> 2);
    const int colbase = bn + wn * 64 + (lane & 3) * 2;

    if constexpr (EPI == 0) {
#pragma unroll
        for (int mt = 0; mt < 4; mt++)
#pragma unroll
            for (int nt = 0; nt < 8; nt++) {
                int col = colbase + nt * 8;
                int rA = rbase + mt * 16, rB = rA + 8;
                *(__nv_bfloat162*)&g_qb[(size_t)rA * DIM + col] =
                    __floats2bfloat162_rn(acc[mt][nt][0], acc[mt][nt][1]);
                *(__nv_bfloat162*)&g_qb[(size_t)rB * DIM + col] =
                    __floats2bfloat162_rn(acc[mt][nt][2], acc[mt][nt][3]);
            }
    } else if constexpr (EPI == 1) {
        const float beta = __ldg(beta_ptr);
#pragma unroll
        for (int mt = 0; mt < 4; mt++) {
            float rs0 = 0.f, rs1 = 0.f;
#pragma unroll
            for (int nt = 0; nt < 8; nt++) {
                int col = colbase + nt * 8;
                int rA = rbase + mt * 16, rB = rA + 8;
                float e0 = __expf(beta * acc[mt][nt][0]);
                float e1 = __expf(beta * acc[mt][nt][1]);
                float e2 = __expf(beta * acc[mt][nt][2]);
                float e3 = __expf(beta * acc[mt][nt][3]);
                rs0 += e0 + e1;
                rs1 += e2 + e3;
                *(__nv_bfloat162*)&g_p[(size_t)rA * NPAT + col] =
                    __floats2bfloat162_rn(e0 - 1.f, e1 - 1.f);
                *(__nv_bfloat162*)&g_p[(size_t)rB * NPAT + col] =
                    __floats2bfloat162_rn(e2 - 1.f, e3 - 1.f);
            }
            rs0 += __shfl_xor_sync(0xffffffffu, rs0, 1);
            rs0 += __shfl_xor_sync(0xffffffffu, rs0, 2);
            rs1 += __shfl_xor_sync(0xffffffffu, rs1, 1);
            rs1 += __shfl_xor_sync(0xffffffffu, rs1, 2);
            if ((lane & 3) == 0) {
                atomicAdd(&g_rowsum[rbase + mt * 16], rs0);
                atomicAdd(&g_rowsum[rbase + mt * 16 + 8], rs1);
            }
        }
    } else {
#pragma unroll
        for (int mt = 0; mt < 4; mt++) {
            float inv0 = 1.f / g_rowsum[rbase + mt * 16];
            float inv1 = 1.f / g_rowsum[rbase + mt * 16 + 8];
#pragma unroll
            for (int nt = 0; nt < 8; nt++) {
                int col = colbase + nt * 8;
                int rA = rbase + mt * 16, rB = rA + 8;
                float cs0 = g_colsum[col], cs1 = g_colsum[col + 1];
                *(float2*)&outp[(size_t)rA * DIM + col] =
                    make_float2((acc[mt][nt][0] + cs0) * inv0,
                                (acc[mt][nt][1] + cs1) * inv0);
                *(float2*)&outp[(size_t)rB * DIM + col] =
                    make_float2((acc[mt][nt][2] + cs0) * inv1,
                                (acc[mt][nt][3] + cs1) * inv1);
            }
        }
    }
}

// ---------------- host ----------------
extern "C" void kernel_launch(void* const* d_in, const int* in_sizes, int n_in,
                              void* d_out, int out_size) {
    const float* x    = (const float*)d_in[0];
    const float* wq   = (const float*)d_in[1];
    const float* xi   = (const float*)d_in[2];
    const float* beta = (const float*)d_in[3];
    float* out = (float*)d_out;

    void *p_xb, *p_wqb, *p_xib, *p_xitb, *p_qb, *p_p;
    cudaGetSymbolAddress(&p_xb, g_xb);
    cudaGetSymbolAddress(&p_wqb, g_wqb);
    cudaGetSymbolAddress(&p_xib, g_xib);
    cudaGetSymbolAddress(&p_xitb, g_xitb);
    cudaGetSymbolAddress(&p_qb, g_qb);
    cudaGetSymbolAddress(&p_p, g_p);

    static bool attr_done = false;
    if (!attr_done) {
        cudaFuncSetAttribute(hgemm<0>, cudaFuncAttributeMaxDynamicSharedMemorySize, DSMEM);
        cudaFuncSetAttribute(hgemm<1>, cudaFuncAttributeMaxDynamicSharedMemorySize, DSMEM);
        cudaFuncSetAttribute(hgemm<2>, cudaFuncAttributeMaxDynamicSharedMemorySize, DSMEM);
        attr_done = true;
    }

    cvt_kernel<<<(NROWS * DIM / 4 + 255) / 256, 256>>>((const float4*)x,  (__nv_bfloat162*)p_xb,  NROWS * DIM / 4);
    cvt_kernel<<<(DIM * DIM / 4 + 255) / 256, 256>>>((const float4*)wq, (__nv_bfloat162*)p_wqb, DIM * DIM / 4);
    cvt_kernel<<<(NPAT * DIM / 4 + 255) / 256, 256>>>((const float4*)xi, (__nv_bfloat162*)p_xib, NPAT * DIM / 4);
    transpose_kernel<<<dim3(NPAT / 32, DIM / 32), dim3(32, 8)>>>(xi);
    zero_kernel<<<(NROWS + 255) / 256, 256>>>();
    colsum_kernel<<<NPAT / 128, 256>>>(xi);

    // q = x * wq^T
    hgemm<0><<<dim3(DIM / BN, NROWS / BM), 256, DSMEM>>>(
        (const __nv_bfloat16*)p_xb, (const __nv_bfloat16*)p_wqb, DIM, DIM, DIM / 64, beta, out);
    // P' = exp(beta * q * xi^T) - 1, rowsum
    hgemm<1><<<dim3(NPAT / BN, NROWS / BM), 256, DSMEM>>>(
        (const __nv_bfloat16*)p_qb, (const __nv_bfloat16*)p_xib, DIM, DIM, DIM / 64, beta, out);
    // out = (P' * xi + colsum) / rowsum
    hgemm<2><<<dim3(DIM / BN, NROWS / BM), 256, DSMEM>>>(
        (const __nv_bfloat16*)p_p, (const __nv_bfloat16*)p_xitb, NPAT, NPAT, NPAT / 64, beta, out);
}

// round 8
// speedup vs baseline: 1.4014x; 1.4014x over previous
#include <cuda_runtime.h>
#include <cuda_bf16.h>
#include <stdint.h>
#include <math.h>

#define DIM   1024
#define NPAT  8192
#define NROWS 8192

__device__ __nv_bfloat16 g_xb  [(size_t)NROWS * DIM];
__device__ __nv_bfloat16 g_wqb [(size_t)DIM * DIM];
__device__ __nv_bfloat16 g_xib [(size_t)NPAT * DIM];
__device__ __nv_bfloat16 g_xitb[(size_t)DIM * NPAT];
__device__ __nv_bfloat16 g_qb  [(size_t)NROWS * DIM];
__device__ __nv_bfloat16 g_p   [(size_t)NROWS * NPAT];
__device__ float g_rowsum[NROWS];
__device__ float g_colsum[DIM];

__device__ __forceinline__ uint32_t smem_u32(const void* p) {
    uint32_t a;
    asm("{ .reg .u64 t; cvta.to.shared.u64 t, %1; cvt.u32.u64 %0, t; }" : "=r"(a) : "l"(p));
    return a;
}
__device__ __forceinline__ uint32_t sw128(uint32_t o) { return o ^ ((o >> 3) & 0x70); }

#define LDMX4(r, a)                                                               \
    asm volatile("ldmatrix.sync.aligned.m8n8.x4.shared.b16 {%0,%1,%2,%3}, [%4];"  \
        : "=r"((r)[0]), "=r"((r)[1]), "=r"((r)[2]), "=r"((r)[3]) : "r"(a))

#define MMA16816(d, a, b0, b1)                                                    \
    asm volatile("mma.sync.aligned.m16n8k16.row.col.f32.bf16.bf16.f32 "           \
        "{%0,%1,%2,%3}, {%4,%5,%6,%7}, {%8,%9}, {%0,%1,%2,%3};"                   \
        : "+f"((d)[0]), "+f"((d)[1]), "+f"((d)[2]), "+f"((d)[3])                  \
        : "r"((a)[0]), "r"((a)[1]), "r"((a)[2]), "r"((a)[3]), "r"(b0), "r"(b1))

#define CP_ASYNC(s, g) \
    asm volatile("cp.async.cg.shared.global [%0], [%1], 16;" :: "r"(s), "l"(g))
#define CP_COMMIT() asm volatile("cp.async.commit_group;")
#define CP_WAIT(n)  asm volatile("cp.async.wait_group %0;" :: "n"(n))

// ---------------- prep kernels ----------------
__global__ void zero_kernel() {
    int i = blockIdx.x * blockDim.x + threadIdx.x;
    if (i < NROWS) g_rowsum[i] = 0.f;
    if (i < DIM)   g_colsum[i] = 0.f;
}
__global__ void cvt_kernel(const float4* __restrict__ src, __nv_bfloat162* __restrict__ dst, int n4) {
    int i = blockIdx.x * blockDim.x + threadIdx.x;
    if (i < n4) {
        float4 v = src[i];
        dst[2 * i]     = __floats2bfloat162_rn(v.x, v.y);
        dst[2 * i + 1] = __floats2bfloat162_rn(v.z, v.w);
    }
}
__global__ void transpose_kernel(const float* __restrict__ xi) {
    __shared__ __nv_bfloat16 t[32][33];
    int p0 = blockIdx.x * 32, d0 = blockIdx.y * 32;
    int tx = threadIdx.x, ty = threadIdx.y;
#pragma unroll
    for (int i = 0; i < 4; i++)
        t[ty + 8 * i][tx] = __float2bfloat16(xi[(size_t)(p0 + ty + 8 * i) * DIM + d0 + tx]);
    __syncthreads();
#pragma unroll
    for (int i = 0; i < 4; i++)
        g_xitb[(size_t)(d0 + ty + 8 * i) * NPAT + p0 + tx] = t[tx][ty + 8 * i];
}
__global__ void colsum_kernel(const float* __restrict__ xi) {
    int t = threadIdx.x;
    int r0 = blockIdx.x * 128;
    float4 a = make_float4(0.f, 0.f, 0.f, 0.f);
    for (int r = 0; r < 128; r++) {
        float4 v = ((const float4*)xi)[(size_t)(r0 + r) * (DIM / 4) + t];
        a.x += v.x; a.y += v.y; a.z += v.z; a.w += v.w;
    }
    atomicAdd(&g_colsum[4 * t + 0], a.x);
    atomicAdd(&g_colsum[4 * t + 1], a.y);
    atomicAdd(&g_colsum[4 * t + 2], a.z);
    atomicAdd(&g_colsum[4 * t + 3], a.w);
}

// =============================================================================
// bf16 HMMA GEMM: C[128x128] = A[128xK] * B[128xK]^T (row-major, K contiguous)
// 256 threads = 8 warps (4m x 2n), warp tile 32x64, mma.m16n8k16, fp32 accum.
// 3-stage cp.async pipeline (BK=64, 32KB/stage), register double-buffered
// fragments, one __syncthreads per K-chunk.
// =============================================================================
#define STAGES 3
#define STAGE_BYTES 32768
#define DSMEM (STAGES * STAGE_BYTES)

__device__ __forceinline__ void issue_stage(uint32_t sdst,
        const __nv_bfloat16* __restrict__ Ag, const __nv_bfloat16* __restrict__ Bg,
        int lda, int ldb, int bm, int bn, int k0, int tid) {
#pragma unroll
    for (int t = 0; t < 4; t++) {
        int id = tid + t * 256, row = id >> 3, c = id & 7;
        CP_ASYNC(sdst + sw128(row * 128 + c * 16),
                 Ag + (size_t)(bm + row) * lda + k0 + c * 8);
    }
#pragma unroll
    for (int t = 0; t < 4; t++) {
        int id = tid + t * 256, row = id >> 3, c = id & 7;
        CP_ASYNC(sdst + 16384 + sw128(row * 128 + c * 16),
                 Bg + (size_t)(bn + row) * ldb + k0 + c * 8);
    }
}

template <int EPI>
__global__ __launch_bounds__(256, 1) void hgemm(
        const __nv_bfloat16* __restrict__ A, const __nv_bfloat16* __restrict__ B,
        int lda, int ldb, int nk,
        const float* __restrict__ beta_ptr, float* __restrict__ outp) {
    extern __shared__ char sm[];
    const uint32_t sb = smem_u32(sm);
    const int tid = threadIdx.x, lane = tid & 31, w = tid >> 5;
    const int wm = w & 3, wn = w >> 2;
    const int bm = blockIdx.y * 128, bn = blockIdx.x * 128;

    float acc[2][8][4];
#pragma unroll
    for (int mt = 0; mt < 2; mt++)
#pragma unroll
        for (int nt = 0; nt < 8; nt++)
#pragma unroll
            for (int j = 0; j < 4; j++) acc[mt][nt][j] = 0.f;

    issue_stage(sb, A, B, lda, ldb, bm, bn, 0, tid);  CP_COMMIT();
    issue_stage(sb + STAGE_BYTES, A, B, lda, ldb, bm, bn, 64, tid);  CP_COMMIT();

    const uint32_t abase0 = (wm * 32 + (lane & 15)) * 128 + (lane >> 4) * 16;
    const uint32_t bbase0 = (wn * 64 + ((lane >> 4) & 1) * 8 + (lane & 7)) * 128 +
                            ((lane >> 3) & 1) * 16;

    for (int i = 0; i < nk; i++) {
        if (i == nk - 1) { CP_WAIT(0); } else { CP_WAIT(1); }
        __syncthreads();
        if (i + 2 < nk) {
            issue_stage(sb + ((i + 2) % STAGES) * STAGE_BYTES, A, B, lda, ldb, bm, bn,
                        (i + 2) * 64, tid);
            CP_COMMIT();
        }
        const uint32_t sA = sb + (i % STAGES) * STAGE_BYTES;
        const uint32_t sB = sA + 16384;

        // register double-buffered fragments
        uint32_t a[2][2][4], b[2][4][4];
#pragma unroll
        for (int mt = 0; mt < 2; mt++)
            LDMX4(a[0][mt], sA + sw128(abase0 + mt * 16 * 128));
#pragma unroll
        for (int nt2 = 0; nt2 < 4; nt2++)
            LDMX4(b[0][nt2], sB + sw128(bbase0 + nt2 * 16 * 128));

#pragma unroll
        for (int ks = 0; ks < 4; ks++) {
            const int cur = ks & 1, nxt = cur ^ 1;
            if (ks < 3) {
#pragma unroll
                for (int mt = 0; mt < 2; mt++)
                    LDMX4(a[nxt][mt], sA + sw128(abase0 + mt * 16 * 128 + (ks + 1) * 32));
#pragma unroll
                for (int nt2 = 0; nt2 < 4; nt2++)
                    LDMX4(b[nxt][nt2], sB + sw128(bbase0 + nt2 * 16 * 128 + (ks + 1) * 32));
            }
#pragma unroll
            for (int mt = 0; mt < 2; mt++)
#pragma unroll
                for (int nt = 0; nt < 8; nt++)
                    MMA16816(acc[mt][nt], a[cur][mt], b[cur][nt >> 1][(nt & 1) * 2],
                             b[cur][nt >> 1][(nt & 1) * 2 + 1]);
        }
    }

    // ------------------------------ epilogue ------------------------------
    const int rbase   = bm + wm * 32 + (lane >> 2);
    const int colbase = bn + wn * 64 + (lane & 3) * 2;

    if constexpr (EPI == 0) {
#pragma unroll
        for (int mt = 0; mt < 2; mt++)
#pragma unroll
            for (int nt = 0; nt < 8; nt++) {
                int col = colbase + nt * 8;
                int rA = rbase + mt * 16, rB = rA + 8;
                *(__nv_bfloat162*)&g_qb[(size_t)rA * DIM + col] =
                    __floats2bfloat162_rn(acc[mt][nt][0], acc[mt][nt][1]);
                *(__nv_bfloat162*)&g_qb[(size_t)rB * DIM + col] =
                    __floats2bfloat162_rn(acc[mt][nt][2], acc[mt][nt][3]);
            }
    } else if constexpr (EPI == 1) {
        const float beta = __ldg(beta_ptr);
        float rs[2][2] = {{0.f, 0.f}, {0.f, 0.f}};
#pragma unroll
        for (int mt = 0; mt < 2; mt++)
#pragma unroll
            for (int nt = 0; nt < 8; nt++) {
                int col = colbase + nt * 8;
                int rA = rbase + mt * 16, rB = rA + 8;
                float e0 = __expf(beta * acc[mt][nt][0]);
                float e1 = __expf(beta * acc[mt][nt][1]);
                float e2 = __expf(beta * acc[mt][nt][2]);
                float e3 = __expf(beta * acc[mt][nt][3]);
                rs[mt][0] += e0 + e1;
                rs[mt][1] += e2 + e3;
                *(__nv_bfloat162*)&g_p[(size_t)rA * NPAT + col] =
                    __floats2bfloat162_rn(e0 - 1.f, e1 - 1.f);
                *(__nv_bfloat162*)&g_p[(size_t)rB * NPAT + col] =
                    __floats2bfloat162_rn(e2 - 1.f, e3 - 1.f);
            }
#pragma unroll
        for (int mt = 0; mt < 2; mt++)
#pragma unroll
            for (int h = 0; h < 2; h++) {
                float v = rs[mt][h];
                v += __shfl_xor_sync(0xffffffffu, v, 1);
                v += __shfl_xor_sync(0xffffffffu, v, 2);
                if ((lane & 3) == 0)
                    atomicAdd(&g_rowsum[rbase + mt * 16 + h * 8], v);
            }
    } else {
        float inv[2][2];
#pragma unroll
        for (int mt = 0; mt < 2; mt++)
#pragma unroll
            for (int h = 0; h < 2; h++)
                inv[mt][h] = 1.f / g_rowsum[rbase + mt * 16 + h * 8];
#pragma unroll
        for (int mt = 0; mt < 2; mt++)
#pragma unroll
            for (int nt = 0; nt < 8; nt++) {
                int col = colbase + nt * 8;
                int rA = rbase + mt * 16, rB = rA + 8;
                float cs0 = g_colsum[col], cs1 = g_colsum[col + 1];
                *(float2*)&outp[(size_t)rA * DIM + col] =
                    make_float2((acc[mt][nt][0] + cs0) * inv[mt][0],
                                (acc[mt][nt][1] + cs1) * inv[mt][0]);
                *(float2*)&outp[(size_t)rB * DIM + col] =
                    make_float2((acc[mt][nt][2] + cs0) * inv[mt][1],
                                (acc[mt][nt][3] + cs1) * inv[mt][1]);
            }
    }
}

// ---------------- host ----------------
extern "C" void kernel_launch(void* const* d_in, const int* in_sizes, int n_in,
                              void* d_out, int out_size) {
    const float* x    = (const float*)d_in[0];
    const float* wq   = (const float*)d_in[1];
    const float* xi   = (const float*)d_in[2];
    const float* beta = (const float*)d_in[3];
    float* out = (float*)d_out;

    void *p_xb, *p_wqb, *p_xib, *p_xitb, *p_qb, *p_p;
    cudaGetSymbolAddress(&p_xb, g_xb);
    cudaGetSymbolAddress(&p_wqb, g_wqb);
    cudaGetSymbolAddress(&p_xib, g_xib);
    cudaGetSymbolAddress(&p_xitb, g_xitb);
    cudaGetSymbolAddress(&p_qb, g_qb);
    cudaGetSymbolAddress(&p_p, g_p);

    static bool attr_done = false;
    if (!attr_done) {
        cudaFuncSetAttribute(hgemm<0>, cudaFuncAttributeMaxDynamicSharedMemorySize, DSMEM);
        cudaFuncSetAttribute(hgemm<1>, cudaFuncAttributeMaxDynamicSharedMemorySize, DSMEM);
        cudaFuncSetAttribute(hgemm<2>, cudaFuncAttributeMaxDynamicSharedMemorySize, DSMEM);
        attr_done = true;
    }

    cvt_kernel<<<(NROWS * DIM / 4 + 255) / 256, 256>>>((const float4*)x,  (__nv_bfloat162*)p_xb,  NROWS * DIM / 4);
    cvt_kernel<<<(DIM * DIM / 4 + 255) / 256, 256>>>((const float4*)wq, (__nv_bfloat162*)p_wqb, DIM * DIM / 4);
    cvt_kernel<<<(NPAT * DIM / 4 + 255) / 256, 256>>>((const float4*)xi, (__nv_bfloat162*)p_xib, NPAT * DIM / 4);
    transpose_kernel<<<dim3(NPAT / 32, DIM / 32), dim3(32, 8)>>>(xi);
    zero_kernel<<<(NROWS + 255) / 256, 256>>>();
    colsum_kernel<<<NPAT / 128, 256>>>(xi);

    // q = x * wq^T
    hgemm<0><<<dim3(DIM / 128, NROWS / 128), 256, DSMEM>>>(
        (const __nv_bfloat16*)p_xb, (const __nv_bfloat16*)p_wqb, DIM, DIM, DIM / 64, beta, out);
    // P' = exp(beta * q * xi^T) - 1, rowsum
    hgemm<1><<<dim3(NPAT / 128, NROWS / 128), 256, DSMEM>>>(
        (const __nv_bfloat16*)p_qb, (const __nv_bfloat16*)p_xib, DIM, DIM, DIM / 64, beta, out);
    // out = (P' * xi + colsum) / rowsum
    hgemm<2><<<dim3(DIM / 128, NROWS / 128), 256, DSMEM>>>(
        (const __nv_bfloat16*)p_p, (const __nv_bfloat16*)p_xitb, NPAT, NPAT, NPAT / 64, beta, out);
}

// round 9
// speedup vs baseline: 1.5750x; 1.1239x over previous
#include <cuda_runtime.h>
#include <cuda_bf16.h>
#include <stdint.h>
#include <math.h>

#define DIM   1024
#define NPAT  8192
#define NROWS 8192

__device__ __nv_bfloat16 g_xb  [(size_t)NROWS * DIM];
__device__ __nv_bfloat16 g_wqb [(size_t)DIM * DIM];
__device__ __nv_bfloat16 g_xib [(size_t)NPAT * DIM];
__device__ __nv_bfloat16 g_xitb[(size_t)DIM * NPAT];
__device__ __nv_bfloat16 g_qb  [(size_t)NROWS * DIM];
__device__ __nv_bfloat16 g_p   [(size_t)NROWS * NPAT];
__device__ float g_rowsum[NROWS];
__device__ float g_colsum[DIM];

__device__ __forceinline__ uint32_t smem_u32(const void* p) {
    uint32_t a;
    asm("{ .reg .u64 t; cvta.to.shared.u64 t, %1; cvt.u32.u64 %0, t; }" : "=r"(a) : "l"(p));
    return a;
}
__device__ __forceinline__ uint32_t sw128(uint32_t o) { return o ^ ((o >> 3) & 0x70); }

#define LDMX4(r, a)                                                               \
    asm volatile("ldmatrix.sync.aligned.m8n8.x4.shared.b16 {%0,%1,%2,%3}, [%4];"  \
        : "=r"((r)[0]), "=r"((r)[1]), "=r"((r)[2]), "=r"((r)[3]) : "r"(a))

#define MMA16816(d, a, b0, b1)                                                    \
    asm volatile("mma.sync.aligned.m16n8k16.row.col.f32.bf16.bf16.f32 "           \
        "{%0,%1,%2,%3}, {%4,%5,%6,%7}, {%8,%9}, {%0,%1,%2,%3};"                   \
        : "+f"((d)[0]), "+f"((d)[1]), "+f"((d)[2]), "+f"((d)[3])                  \
        : "r"((a)[0]), "r"((a)[1]), "r"((a)[2]), "r"((a)[3]), "r"(b0), "r"(b1))

#define CP_ASYNC(s, g) \
    asm volatile("cp.async.cg.shared.global [%0], [%1], 16;" :: "r"(s), "l"(g))
#define CP_COMMIT() asm volatile("cp.async.commit_group;")
#define CP_WAIT(n)  asm volatile("cp.async.wait_group %0;" :: "n"(n))

// ---------------- prep kernels ----------------
__global__ void zero_kernel() {
    int i = blockIdx.x * blockDim.x + threadIdx.x;
    if (i < NROWS) g_rowsum[i] = 0.f;
    if (i < DIM)   g_colsum[i] = 0.f;
}
__global__ void cvt_kernel(const float4* __restrict__ src, __nv_bfloat162* __restrict__ dst, int n4) {
    int i = blockIdx.x * blockDim.x + threadIdx.x;
    if (i < n4) {
        float4 v = src[i];
        dst[2 * i]     = __floats2bfloat162_rn(v.x, v.y);
        dst[2 * i + 1] = __floats2bfloat162_rn(v.z, v.w);
    }
}
__global__ void transpose_kernel(const float* __restrict__ xi) {
    __shared__ __nv_bfloat16 t[32][33];
    int p0 = blockIdx.x * 32, d0 = blockIdx.y * 32;
    int tx = threadIdx.x, ty = threadIdx.y;
#pragma unroll
    for (int i = 0; i < 4; i++)
        t[ty + 8 * i][tx] = __float2bfloat16(xi[(size_t)(p0 + ty + 8 * i) * DIM + d0 + tx]);
    __syncthreads();
#pragma unroll
    for (int i = 0; i < 4; i++)
        g_xitb[(size_t)(d0 + ty + 8 * i) * NPAT + p0 + tx] = t[tx][ty + 8 * i];
}
__global__ void colsum_kernel(const float* __restrict__ xi) {
    int t = threadIdx.x;
    int r0 = blockIdx.x * 128;
    float4 a = make_float4(0.f, 0.f, 0.f, 0.f);
    for (int r = 0; r < 128; r++) {
        float4 v = ((const float4*)xi)[(size_t)(r0 + r) * (DIM / 4) + t];
        a.x += v.x; a.y += v.y; a.z += v.z; a.w += v.w;
    }
    atomicAdd(&g_colsum[4 * t + 0], a.x);
    atomicAdd(&g_colsum[4 * t + 1], a.y);
    atomicAdd(&g_colsum[4 * t + 2], a.z);
    atomicAdd(&g_colsum[4 * t + 3], a.w);
}

// =============================================================================
// bf16 HMMA GEMM: C[128x256] = A[128xK] * B[256xK]^T (row-major, K contiguous)
// 512 threads = 16 warps (4m x 4n), warp tile 32x64 (acc 64 regs), m16n8k16.
// 3-stage cp.async pipeline (BK=64, 48KB/stage), single-buffered fragments,
// one __syncthreads per K-chunk, 4 warps/SMSP for latency hiding.
// =============================================================================
#define BM 128
#define BN 256
#define A_STG 16384
#define B_STG 32768
#define STAGE_BYTES (A_STG + B_STG)
#define STAGES 3
#define DSMEM (STAGES * STAGE_BYTES)
#define NTHR 512

__device__ __forceinline__ void issue_stage(uint32_t sdst,
        const __nv_bfloat16* __restrict__ Ag, const __nv_bfloat16* __restrict__ Bg,
        int lda, int ldb, int bm, int bn, int k0, int tid) {
#pragma unroll
    for (int t = 0; t < 2; t++) {
        int id = tid + t * NTHR, row = id >> 3, c = id & 7;
        CP_ASYNC(sdst + sw128(row * 128 + c * 16),
                 Ag + (size_t)(bm + row) * lda + k0 + c * 8);
    }
#pragma unroll
    for (int t = 0; t < 4; t++) {
        int id = tid + t * NTHR, row = id >> 3, c = id & 7;
        CP_ASYNC(sdst + A_STG + sw128(row * 128 + c * 16),
                 Bg + (size_t)(bn + row) * ldb + k0 + c * 8);
    }
}

template <int EPI>
__global__ __launch_bounds__(NTHR, 1) void hgemm(
        const __nv_bfloat16* __restrict__ A, const __nv_bfloat16* __restrict__ B,
        int lda, int ldb, int nk,
        const float* __restrict__ beta_ptr, float* __restrict__ outp) {
    extern __shared__ char sm[];
    const uint32_t sb = smem_u32(sm);
    const int tid = threadIdx.x, lane = tid & 31, w = tid >> 5;
    const int wm = w & 3, wn = w >> 2;          // 4m x 4n warps, warp tile 32x64
    const int bm = blockIdx.y * BM, bn = blockIdx.x * BN;

    float acc[2][8][4];
#pragma unroll
    for (int mt = 0; mt < 2; mt++)
#pragma unroll
        for (int nt = 0; nt < 8; nt++)
#pragma unroll
            for (int j = 0; j < 4; j++) acc[mt][nt][j] = 0.f;

    issue_stage(sb, A, B, lda, ldb, bm, bn, 0, tid);  CP_COMMIT();
    issue_stage(sb + STAGE_BYTES, A, B, lda, ldb, bm, bn, 64, tid);  CP_COMMIT();

    const uint32_t abase0 = (wm * 32 + (lane & 15)) * 128 + (lane >> 4) * 16;
    const uint32_t bbase0 = (wn * 64 + ((lane >> 4) & 1) * 8 + (lane & 7)) * 128 +
                            ((lane >> 3) & 1) * 16;

    for (int i = 0; i < nk; i++) {
        if (i == nk - 1) { CP_WAIT(0); } else { CP_WAIT(1); }
        __syncthreads();
        if (i + 2 < nk) {
            issue_stage(sb + ((i + 2) % STAGES) * STAGE_BYTES, A, B, lda, ldb, bm, bn,
                        (i + 2) * 64, tid);
            CP_COMMIT();
        }
        const uint32_t sA = sb + (i % STAGES) * STAGE_BYTES;
        const uint32_t sB = sA + A_STG;
#pragma unroll
        for (int ks = 0; ks < 4; ks++) {
            uint32_t a[2][4], b[4][4];
#pragma unroll
            for (int mt = 0; mt < 2; mt++)
                LDMX4(a[mt], sA + sw128(abase0 + mt * 16 * 128 + ks * 32));
#pragma unroll
            for (int nt2 = 0; nt2 < 4; nt2++)
                LDMX4(b[nt2], sB + sw128(bbase0 + nt2 * 16 * 128 + ks * 32));
#pragma unroll
            for (int mt = 0; mt < 2; mt++)
#pragma unroll
                for (int nt = 0; nt < 8; nt++)
                    MMA16816(acc[mt][nt], a[mt], b[nt >> 1][(nt & 1) * 2],
                             b[nt >> 1][(nt & 1) * 2 + 1]);
        }
    }

    // ------------------------------ epilogue ------------------------------
    const int rbase   = bm + wm * 32 + (lane >> 2);
    const int colbase = bn + wn * 64 + (lane & 3) * 2;

    if constexpr (EPI == 0) {
#pragma unroll
        for (int mt = 0; mt < 2; mt++)
#pragma unroll
            for (int nt = 0; nt < 8; nt++) {
                int col = colbase + nt * 8;
                int rA = rbase + mt * 16, rB = rA + 8;
                *(__nv_bfloat162*)&g_qb[(size_t)rA * DIM + col] =
                    __floats2bfloat162_rn(acc[mt][nt][0], acc[mt][nt][1]);
                *(__nv_bfloat162*)&g_qb[(size_t)rB * DIM + col] =
                    __floats2bfloat162_rn(acc[mt][nt][2], acc[mt][nt][3]);
            }
    } else if constexpr (EPI == 1) {
        const float beta = __ldg(beta_ptr);
        float rs[2][2] = {{0.f, 0.f}, {0.f, 0.f}};
#pragma unroll
        for (int mt = 0; mt < 2; mt++)
#pragma unroll
            for (int nt = 0; nt < 8; nt++) {
                int col = colbase + nt * 8;
                int rA = rbase + mt * 16, rB = rA + 8;
                float e0 = __expf(beta * acc[mt][nt][0]);
                float e1 = __expf(beta * acc[mt][nt][1]);
                float e2 = __expf(beta * acc[mt][nt][2]);
                float e3 = __expf(beta * acc[mt][nt][3]);
                rs[mt][0] += e0 + e1;
                rs[mt][1] += e2 + e3;
                *(__nv_bfloat162*)&g_p[(size_t)rA * NPAT + col] =
                    __floats2bfloat162_rn(e0 - 1.f, e1 - 1.f);
                *(__nv_bfloat162*)&g_p[(size_t)rB * NPAT + col] =
                    __floats2bfloat162_rn(e2 - 1.f, e3 - 1.f);
            }
#pragma unroll
        for (int mt = 0; mt < 2; mt++)
#pragma unroll
            for (int h = 0; h < 2; h++) {
                float v = rs[mt][h];
                v += __shfl_xor_sync(0xffffffffu, v, 1);
                v += __shfl_xor_sync(0xffffffffu, v, 2);
                if ((lane & 3) == 0)
                    atomicAdd(&g_rowsum[rbase + mt * 16 + h * 8], v);
            }
    } else {
        float inv[2][2];
#pragma unroll
        for (int mt = 0; mt < 2; mt++)
#pragma unroll
            for (int h = 0; h < 2; h++)
                inv[mt][h] = 1.f / g_rowsum[rbase + mt * 16 + h * 8];
#pragma unroll
        for (int mt = 0; mt < 2; mt++)
#pragma unroll
            for (int nt = 0; nt < 8; nt++) {
                int col = colbase + nt * 8;
                int rA = rbase + mt * 16, rB = rA + 8;
                float cs0 = g_colsum[col], cs1 = g_colsum[col + 1];
                *(float2*)&outp[(size_t)rA * DIM + col] =
                    make_float2((acc[mt][nt][0] + cs0) * inv[mt][0],
                                (acc[mt][nt][1] + cs1) * inv[mt][0]);
                *(float2*)&outp[(size_t)rB * DIM + col] =
                    make_float2((acc[mt][nt][2] + cs0) * inv[mt][1],
                                (acc[mt][nt][3] + cs1) * inv[mt][1]);
            }
    }
}

// ---------------- host ----------------
extern "C" void kernel_launch(void* const* d_in, const int* in_sizes, int n_in,
                              void* d_out, int out_size) {
    const float* x    = (const float*)d_in[0];
    const float* wq   = (const float*)d_in[1];
    const float* xi   = (const float*)d_in[2];
    const float* beta = (const float*)d_in[3];
    float* out = (float*)d_out;

    void *p_xb, *p_wqb, *p_xib, *p_xitb, *p_qb, *p_p;
    cudaGetSymbolAddress(&p_xb, g_xb);
    cudaGetSymbolAddress(&p_wqb, g_wqb);
    cudaGetSymbolAddress(&p_xib, g_xib);
    cudaGetSymbolAddress(&p_xitb, g_xitb);
    cudaGetSymbolAddress(&p_qb, g_qb);
    cudaGetSymbolAddress(&p_p, g_p);

    static bool attr_done = false;
    if (!attr_done) {
        cudaFuncSetAttribute(hgemm<0>, cudaFuncAttributeMaxDynamicSharedMemorySize, DSMEM);
        cudaFuncSetAttribute(hgemm<1>, cudaFuncAttributeMaxDynamicSharedMemorySize, DSMEM);
        cudaFuncSetAttribute(hgemm<2>, cudaFuncAttributeMaxDynamicSharedMemorySize, DSMEM);
        attr_done = true;
    }

    cvt_kernel<<<(NROWS * DIM / 4 + 255) / 256, 256>>>((const float4*)x,  (__nv_bfloat162*)p_xb,  NROWS * DIM / 4);
    cvt_kernel<<<(DIM * DIM / 4 + 255) / 256, 256>>>((const float4*)wq, (__nv_bfloat162*)p_wqb, DIM * DIM / 4);
    cvt_kernel<<<(NPAT * DIM / 4 + 255) / 256, 256>>>((const float4*)xi, (__nv_bfloat162*)p_xib, NPAT * DIM / 4);
    transpose_kernel<<<dim3(NPAT / 32, DIM / 32), dim3(32, 8)>>>(xi);
    zero_kernel<<<(NROWS + 255) / 256, 256>>>();
    colsum_kernel<<<NPAT / 128, 256>>>(xi);

    // q = x * wq^T
    hgemm<0><<<dim3(DIM / BN, NROWS / BM), NTHR, DSMEM>>>(
        (const __nv_bfloat16*)p_xb, (const __nv_bfloat16*)p_wqb, DIM, DIM, DIM / 64, beta, out);
    // P' = exp(beta * q * xi^T) - 1, rowsum
    hgemm<1><<<dim3(NPAT / BN, NROWS / BM), NTHR, DSMEM>>>(
        (const __nv_bfloat16*)p_qb, (const __nv_bfloat16*)p_xib, DIM, DIM, DIM / 64, beta, out);
    // out = (P' * xi + colsum) / rowsum
    hgemm<2><<<dim3(DIM / BN, NROWS / BM), NTHR, DSMEM>>>(
        (const __nv_bfloat16*)p_p, (const __nv_bfloat16*)p_xitb, NPAT, NPAT, NPAT / 64, beta, out);
}

// round 14
// speedup vs baseline: 1.6008x; 1.0164x over previous
#include <cuda_runtime.h>
#include <cuda_bf16.h>
#include <stdint.h>
#include <math.h>

#define DIM   1024
#define NPAT  8192
#define NROWS 8192

__device__ __nv_bfloat16 g_xb  [(size_t)NROWS * DIM];
__device__ __nv_bfloat16 g_wqb [(size_t)DIM * DIM];
__device__ __nv_bfloat16 g_xib [(size_t)NPAT * DIM];
__device__ __nv_bfloat16 g_xitb[(size_t)DIM * NPAT];
__device__ __nv_bfloat16 g_qb  [(size_t)NROWS * DIM];
__device__ __nv_bfloat16 g_p   [(size_t)NROWS * NPAT];
__device__ float g_rowsum[NROWS];
__device__ float g_colsum[DIM];

__device__ __forceinline__ uint32_t smem_u32(const void* p) {
    uint32_t a;
    asm("{ .reg .u64 t; cvta.to.shared.u64 t, %1; cvt.u32.u64 %0, t; }" : "=r"(a) : "l"(p));
    return a;
}
__device__ __forceinline__ uint32_t sw128(uint32_t o) { return o ^ ((o >> 3) & 0x70); }

#define LDMX4(r, a)                                                               \
    asm volatile("ldmatrix.sync.aligned.m8n8.x4.shared.b16 {%0,%1,%2,%3}, [%4];"  \
        : "=r"((r)[0]), "=r"((r)[1]), "=r"((r)[2]), "=r"((r)[3]) : "r"(a))

#define MMA16816(d, a, b0, b1)                                                    \
    asm volatile("mma.sync.aligned.m16n8k16.row.col.f32.bf16.bf16.f32 "           \
        "{%0,%1,%2,%3}, {%4,%5,%6,%7}, {%8,%9}, {%0,%1,%2,%3};"                   \
        : "+f"((d)[0]), "+f"((d)[1]), "+f"((d)[2]), "+f"((d)[3])                  \
        : "r"((a)[0]), "r"((a)[1]), "r"((a)[2]), "r"((a)[3]), "r"(b0), "r"(b1))

#define CP_ASYNC(s, g) \
    asm volatile("cp.async.cg.shared.global [%0], [%1], 16;" :: "r"(s), "l"(g))
#define CP_COMMIT() asm volatile("cp.async.commit_group;")
#define CP_WAIT(n)  asm volatile("cp.async.wait_group %0;" :: "n"(n))

// ---------------- prep kernels ----------------
__global__ void zero_kernel() {
    int i = blockIdx.x * blockDim.x + threadIdx.x;
    if (i < NROWS) g_rowsum[i] = 0.f;
    if (i < DIM)   g_colsum[i] = 0.f;
}
__global__ void cvt_kernel(const float4* __restrict__ src, __nv_bfloat162* __restrict__ dst, int n4) {
    int i = blockIdx.x * blockDim.x + threadIdx.x;
    if (i < n4) {
        float4 v = src[i];
        dst[2 * i]     = __floats2bfloat162_rn(v.x, v.y);
        dst[2 * i + 1] = __floats2bfloat162_rn(v.z, v.w);
    }
}
__global__ void transpose_kernel(const float* __restrict__ xi) {
    __shared__ __nv_bfloat16 t[32][33];
    int p0 = blockIdx.x * 32, d0 = blockIdx.y * 32;
    int tx = threadIdx.x, ty = threadIdx.y;
#pragma unroll
    for (int i = 0; i < 4; i++)
        t[ty + 8 * i][tx] = __float2bfloat16(xi[(size_t)(p0 + ty + 8 * i) * DIM + d0 + tx]);
    __syncthreads();
#pragma unroll
    for (int i = 0; i < 4; i++)
        g_xitb[(size_t)(d0 + ty + 8 * i) * NPAT + p0 + tx] = t[tx][ty + 8 * i];
}
__global__ void colsum_kernel(const float* __restrict__ xi) {
    int t = threadIdx.x;
    int r0 = blockIdx.x * 128;
    float4 a = make_float4(0.f, 0.f, 0.f, 0.f);
    for (int r = 0; r < 128; r++) {
        float4 v = ((const float4*)xi)[(size_t)(r0 + r) * (DIM / 4) + t];
        a.x += v.x; a.y += v.y; a.z += v.z; a.w += v.w;
    }
    atomicAdd(&g_colsum[4 * t + 0], a.x);
    atomicAdd(&g_colsum[4 * t + 1], a.y);
    atomicAdd(&g_colsum[4 * t + 2], a.z);
    atomicAdd(&g_colsum[4 * t + 3], a.w);
}

// =============================================================================
// bf16 HMMA GEMM: C[128x128] = A[128xK] * B[128xK]^T (row-major, K contiguous)
// 256 threads = 8 warps (4m x 2n), warp tile 32x64, m16n8k16, fp32 accum.
// 3-stage cp.async (BK=64, 32KB/stage = 96KB), __launch_bounds__(256, 2):
// TWO CTAs per SM so barrier/LDSM bursts of one CTA are hidden by the other.
// =============================================================================
#define STAGES 3
#define STAGE_BYTES 32768
#define DSMEM (STAGES * STAGE_BYTES)

__device__ __forceinline__ void issue_stage(uint32_t sdst,
        const __nv_bfloat16* __restrict__ Ag, const __nv_bfloat16* __restrict__ Bg,
        int lda, int ldb, int bm, int bn, int k0, int tid) {
#pragma unroll
    for (int t = 0; t < 4; t++) {
        int id = tid + t * 256, row = id >> 3, c = id & 7;
        CP_ASYNC(sdst + sw128(row * 128 + c * 16),
                 Ag + (size_t)(bm + row) * lda + k0 + c * 8);
    }
#pragma unroll
    for (int t = 0; t < 4; t++) {
        int id = tid + t * 256, row = id >> 3, c = id & 7;
        CP_ASYNC(sdst + 16384 + sw128(row * 128 + c * 16),
                 Bg + (size_t)(bn + row) * ldb + k0 + c * 8);
    }
}

template <int EPI>
__global__ __launch_bounds__(256, 2) void hgemm(
        const __nv_bfloat16* __restrict__ A, const __nv_bfloat16* __restrict__ B,
        int lda, int ldb, int nk,
        const float* __restrict__ beta_ptr, float* __restrict__ outp) {
    extern __shared__ char sm[];
    const uint32_t sb = smem_u32(sm);
    const int tid = threadIdx.x, lane = tid & 31, w = tid >> 5;
    const int wm = w & 3, wn = w >> 2;
    const int bm = blockIdx.y * 128, bn = blockIdx.x * 128;

    float acc[2][8][4];
#pragma unroll
    for (int mt = 0; mt < 2; mt++)
#pragma unroll
        for (int nt = 0; nt < 8; nt++)
#pragma unroll
            for (int j = 0; j < 4; j++) acc[mt][nt][j] = 0.f;

    issue_stage(sb, A, B, lda, ldb, bm, bn, 0, tid);  CP_COMMIT();
    issue_stage(sb + STAGE_BYTES, A, B, lda, ldb, bm, bn, 64, tid);  CP_COMMIT();

    const uint32_t abase0 = (wm * 32 + (lane & 15)) * 128 + (lane >> 4) * 16;
    const uint32_t bbase0 = (wn * 64 + ((lane >> 4) & 1) * 8 + (lane & 7)) * 128 +
                            ((lane >> 3) & 1) * 16;

    for (int i = 0; i < nk; i++) {
        if (i == nk - 1) { CP_WAIT(0); } else { CP_WAIT(1); }
        __syncthreads();
        if (i + 2 < nk) {
            issue_stage(sb + ((i + 2) % STAGES) * STAGE_BYTES, A, B, lda, ldb, bm, bn,
                        (i + 2) * 64, tid);
            CP_COMMIT();
        }
        const uint32_t sA = sb + (i % STAGES) * STAGE_BYTES;
        const uint32_t sB = sA + 16384;
#pragma unroll
        for (int ks = 0; ks < 4; ks++) {
            uint32_t a[2][4], b[4][4];
#pragma unroll
            for (int mt = 0; mt < 2; mt++)
                LDMX4(a[mt], sA + sw128(abase0 + mt * 16 * 128 + ks * 32));
#pragma unroll
            for (int nt2 = 0; nt2 < 4; nt2++)
                LDMX4(b[nt2], sB + sw128(bbase0 + nt2 * 16 * 128 + ks * 32));
#pragma unroll
            for (int mt = 0; mt < 2; mt++)
#pragma unroll
                for (int nt = 0; nt < 8; nt++)
                    MMA16816(acc[mt][nt], a[mt], b[nt >> 1][(nt & 1) * 2],
                             b[nt >> 1][(nt & 1) * 2 + 1]);
        }
    }

    // ------------------------------ epilogue ------------------------------
    const int rbase   = bm + wm * 32 + (lane >> 2);
    const int colbase = bn + wn * 64 + (lane & 3) * 2;

    if constexpr (EPI == 0) {
#pragma unroll
        for (int mt = 0; mt < 2; mt++)
#pragma unroll
            for (int nt = 0; nt < 8; nt++) {
                int col = colbase + nt * 8;
                int rA = rbase + mt * 16, rB = rA + 8;
                *(__nv_bfloat162*)&g_qb[(size_t)rA * DIM + col] =
                    __floats2bfloat162_rn(acc[mt][nt][0], acc[mt][nt][1]);
                *(__nv_bfloat162*)&g_qb[(size_t)rB * DIM + col] =
                    __floats2bfloat162_rn(acc[mt][nt][2], acc[mt][nt][3]);
            }
    } else if constexpr (EPI == 1) {
        const float beta = __ldg(beta_ptr);
        float rs[2][2] = {{0.f, 0.f}, {0.f, 0.f}};
#pragma unroll
        for (int mt = 0; mt < 2; mt++)
#pragma unroll
            for (int nt = 0; nt < 8; nt++) {
                int col = colbase + nt * 8;
                int rA = rbase + mt * 16, rB = rA + 8;
                float e0 = __expf(beta * acc[mt][nt][0]);
                float e1 = __expf(beta * acc[mt][nt][1]);
                float e2 = __expf(beta * acc[mt][nt][2]);
                float e3 = __expf(beta * acc[mt][nt][3]);
                rs[mt][0] += e0 + e1;
                rs[mt][1] += e2 + e3;
                *(__nv_bfloat162*)&g_p[(size_t)rA * NPAT + col] =
                    __floats2bfloat162_rn(e0 - 1.f, e1 - 1.f);
                *(__nv_bfloat162*)&g_p[(size_t)rB * NPAT + col] =
                    __floats2bfloat162_rn(e2 - 1.f, e3 - 1.f);
            }
#pragma unroll
        for (int mt = 0; mt < 2; mt++)
#pragma unroll
            for (int h = 0; h < 2; h++) {
                float v = rs[mt][h];
                v += __shfl_xor_sync(0xffffffffu, v, 1);
                v += __shfl_xor_sync(0xffffffffu, v, 2);
                if ((lane & 3) == 0)
                    atomicAdd(&g_rowsum[rbase + mt * 16 + h * 8], v);
            }
    } else {
        float inv[2][2];
#pragma unroll
        for (int mt = 0; mt < 2; mt++)
#pragma unroll
            for (int h = 0; h < 2; h++)
                inv[mt][h] = 1.f / g_rowsum[rbase + mt * 16 + h * 8];
#pragma unroll
        for (int mt = 0; mt < 2; mt++)
#pragma unroll
            for (int nt = 0; nt < 8; nt++) {
                int col = colbase + nt * 8;
                int rA = rbase + mt * 16, rB = rA + 8;
                float cs0 = g_colsum[col], cs1 = g_colsum[col + 1];
                *(float2*)&outp[(size_t)rA * DIM + col] =
                    make_float2((acc[mt][nt][0] + cs0) * inv[mt][0],
                                (acc[mt][nt][1] + cs1) * inv[mt][0]);
                *(float2*)&outp[(size_t)rB * DIM + col] =
                    make_float2((acc[mt][nt][2] + cs0) * inv[mt][1],
                                (acc[mt][nt][3] + cs1) * inv[mt][1]);
            }
    }
}

// ---------------- host ----------------
extern "C" void kernel_launch(void* const* d_in, const int* in_sizes, int n_in,
                              void* d_out, int out_size) {
    const float* x    = (const float*)d_in[0];
    const float* wq   = (const float*)d_in[1];
    const float* xi   = (const float*)d_in[2];
    const float* beta = (const float*)d_in[3];
    float* out = (float*)d_out;

    void *p_xb, *p_wqb, *p_xib, *p_xitb, *p_qb, *p_p;
    cudaGetSymbolAddress(&p_xb, g_xb);
    cudaGetSymbolAddress(&p_wqb, g_wqb);
    cudaGetSymbolAddress(&p_xib, g_xib);
    cudaGetSymbolAddress(&p_xitb, g_xitb);
    cudaGetSymbolAddress(&p_qb, g_qb);
    cudaGetSymbolAddress(&p_p, g_p);

    static bool attr_done = false;
    if (!attr_done) {
        cudaFuncSetAttribute(hgemm<0>, cudaFuncAttributeMaxDynamicSharedMemorySize, DSMEM);
        cudaFuncSetAttribute(hgemm<1>, cudaFuncAttributeMaxDynamicSharedMemorySize, DSMEM);
        cudaFuncSetAttribute(hgemm<2>, cudaFuncAttributeMaxDynamicSharedMemorySize, DSMEM);
        attr_done = true;
    }

    cvt_kernel<<<(NROWS * DIM / 4 + 255) / 256, 256>>>((const float4*)x,  (__nv_bfloat162*)p_xb,  NROWS * DIM / 4);
    cvt_kernel<<<(DIM * DIM / 4 + 255) / 256, 256>>>((const float4*)wq, (__nv_bfloat162*)p_wqb, DIM * DIM / 4);
    cvt_kernel<<<(NPAT * DIM / 4 + 255) / 256, 256>>>((const float4*)xi, (__nv_bfloat162*)p_xib, NPAT * DIM / 4);
    transpose_kernel<<<dim3(NPAT / 32, DIM / 32), dim3(32, 8)>>>(xi);
    zero_kernel<<<(NROWS + 255) / 256, 256>>>();
    colsum_kernel<<<NPAT / 128, 256>>>(xi);

    // q = x * wq^T
    hgemm<0><<<dim3(DIM / 128, NROWS / 128), 256, DSMEM>>>(
        (const __nv_bfloat16*)p_xb, (const __nv_bfloat16*)p_wqb, DIM, DIM, DIM / 64, beta, out);
    // P' = exp(beta * q * xi^T) - 1, rowsum
    hgemm<1><<<dim3(NPAT / 128, NROWS / 128), 256, DSMEM>>>(
        (const __nv_bfloat16*)p_qb, (const __nv_bfloat16*)p_xib, DIM, DIM, DIM / 64, beta, out);
    // out = (P' * xi + colsum) / rowsum
    hgemm<2><<<dim3(DIM / 128, NROWS / 128), 256, DSMEM>>>(
        (const __nv_bfloat16*)p_p, (const __nv_bfloat16*)p_xitb, NPAT, NPAT, NPAT / 64, beta, out);
}